// round 17
// baseline (speedup 1.0000x reference)
#include <cuda_runtime.h>
#include <math.h>

#define CCH   256
#define HW    384
#define NPIX  (HW*HW)        // 147456 elems per channel
#define NQ    (NPIX/4)       // 36864 float4 per channel
#define QPR   (HW/4)         // 96 float4 per row
#define QPB   1024           // float4 per presum/fixup block
#define BPC   (NQ/QPB)       // 36 blocks per channel
#define INVN  (1.0f/(382.0f*382.0f))

// All scratch slots written every launch by unique owners -> no init kernel.
__device__ float g_part[2][CCH][BPC];    // bulk-sum partials per input
__device__ float g_row [2][CCH][4];      // row sums, rows {0,1,382,383}
__device__ float g_col [2][CCH][4];      // col sums, cols {0,1,382,383}
__device__ float g_corn[2][CCH][16];     // [row class][col class]
__device__ float g_cf  [2][CCH];         // final combine coefficients

// ---------------------------------------------------------------------------
// Kernel 1: presum + bulk partial sums, in the PROVEN 4-quad combine shape
// (R15 measured ~7.3TB/s with loads+adds+stores). Writes out = in1+in2
// (final answer for (1,1) channels) and per-block partial sums of each input.
// ---------------------------------------------------------------------------
__global__ void __launch_bounds__(256) presum_kernel(const float4* __restrict__ in1,
                                                     const float4* __restrict__ in2,
                                                     float4* __restrict__ out) {
    const int blk  = blockIdx.x;
    const int ch   = blk / BPC;
    const int lblk = blk - ch * BPC;
    const size_t base = (size_t)blk * QPB + threadIdx.x;

    float4 a0 = __ldcs(in1 + base);
    float4 a1 = __ldcs(in1 + base + 256);
    float4 a2 = __ldcs(in1 + base + 512);
    float4 a3 = __ldcs(in1 + base + 768);
    float4 b0 = __ldcs(in2 + base);
    float4 b1 = __ldcs(in2 + base + 256);
    float4 b2 = __ldcs(in2 + base + 512);
    float4 b3 = __ldcs(in2 + base + 768);

    float4 o;
    o.x = a0.x + b0.x; o.y = a0.y + b0.y; o.z = a0.z + b0.z; o.w = a0.w + b0.w;
    __stcs(out + base, o);
    o.x = a1.x + b1.x; o.y = a1.y + b1.y; o.z = a1.z + b1.z; o.w = a1.w + b1.w;
    __stcs(out + base + 256, o);
    o.x = a2.x + b2.x; o.y = a2.y + b2.y; o.z = a2.z + b2.z; o.w = a2.w + b2.w;
    __stcs(out + base + 512, o);
    o.x = a3.x + b3.x; o.y = a3.y + b3.y; o.z = a3.z + b3.z; o.w = a3.w + b3.w;
    __stcs(out + base + 768, o);

    float sA = (((a0.x + a0.y) + (a0.z + a0.w)) + ((a1.x + a1.y) + (a1.z + a1.w)))
             + (((a2.x + a2.y) + (a2.z + a2.w)) + ((a3.x + a3.y) + (a3.z + a3.w)));
    float sB = (((b0.x + b0.y) + (b0.z + b0.w)) + ((b1.x + b1.y) + (b1.z + b1.w)))
             + (((b2.x + b2.y) + (b2.z + b2.w)) + ((b3.x + b3.y) + (b3.z + b3.w)));

    #pragma unroll
    for (int off = 16; off > 0; off >>= 1) {
        sA += __shfl_down_sync(0xffffffffu, sA, off);
        sB += __shfl_down_sync(0xffffffffu, sB, off);
    }
    __shared__ float redA[8], redB[8];
    const int warp = threadIdx.x >> 5, lane = threadIdx.x & 31;
    if (lane == 0) { redA[warp] = sA; redB[warp] = sB; }
    __syncthreads();
    if (threadIdx.x == 0) {
        float TA = ((redA[0] + redA[1]) + (redA[2] + redA[3]))
                 + ((redA[4] + redA[5]) + (redA[6] + redA[7]));
        float TB = ((redB[0] + redB[1]) + (redB[2] + redB[3]))
                 + ((redB[4] + redB[5]) + (redB[6] + redB[7]));
        g_part[0][ch][lblk] = TA;
        g_part[1][ch][lblk] = TB;
    }
}

// ---------------------------------------------------------------------------
// Kernel 2: border stats (verbatim from R11, which passed). grid (CCH, 2),
// block 128. Col sums over all rows + corners; border row sums per warp.
// ---------------------------------------------------------------------------
__global__ void __launch_bounds__(128) border_kernel(const float* __restrict__ in1,
                                                     const float* __restrict__ in2) {
    const int c     = blockIdx.x;
    const int which = blockIdx.y;
    const float4* x = ((const float4*)(which ? in2 : in1)) + (size_t)c * NQ;

    const int tid  = threadIdx.x;
    const int warp = tid >> 5, lane = tid & 31;

    // ---- Phase A: column sums + corners ----
    float c0 = 0.0f, c1 = 0.0f, c2 = 0.0f, c3 = 0.0f;
    #pragma unroll
    for (int k = 0; k < 3; k++) {
        const int r = tid + k * 128;
        float4 a = __ldg(x + (size_t)r * QPR);            // cols 0..3
        float4 b = __ldg(x + (size_t)r * QPR + 95);       // cols 380..383
        c0 += a.x; c1 += a.y; c2 += b.z; c3 += b.w;
        if (r <= 1 || r >= 382) {
            const int rc = (r <= 1) ? r : (r - 380);      // 0..3
            g_corn[which][c][rc*4 + 0] = a.x;
            g_corn[which][c][rc*4 + 1] = a.y;
            g_corn[which][c][rc*4 + 2] = b.z;
            g_corn[which][c][rc*4 + 3] = b.w;
        }
    }
    #pragma unroll
    for (int off = 16; off > 0; off >>= 1) {
        c0 += __shfl_down_sync(0xffffffffu, c0, off);
        c1 += __shfl_down_sync(0xffffffffu, c1, off);
        c2 += __shfl_down_sync(0xffffffffu, c2, off);
        c3 += __shfl_down_sync(0xffffffffu, c3, off);
    }
    __shared__ float cw[4][4];
    if (lane == 0) { cw[warp][0] = c0; cw[warp][1] = c1; cw[warp][2] = c2; cw[warp][3] = c3; }
    __syncthreads();
    if (tid < 4)
        g_col[which][c][tid] = cw[0][tid] + cw[1][tid] + cw[2][tid] + cw[3][tid];

    // ---- Phase B: border row sums (warp w -> row RR[w]) ----
    const int RR[4] = { 0, 1, 382, 383 };
    const int R = RR[warp];
    float rs = 0.0f;
    #pragma unroll
    for (int k = 0; k < 3; k++) {
        float4 v = __ldg(x + (size_t)R * QPR + lane + k * 32);
        rs += (v.x + v.y) + (v.z + v.w);
    }
    #pragma unroll
    for (int off = 16; off > 0; off >>= 1)
        rs += __shfl_down_sync(0xffffffffu, rs, off);
    if (lane == 0) g_row[which][c][warp] = rs;
}

// ---------------------------------------------------------------------------
// Kernel 3: finalize (partials + borders -> 9 window sums per input-channel)
// fused with the per-oc matvec, sigmoid, branch flags -> coefficients.
// (R11 structure; passed with rel_err 0.)
// ---------------------------------------------------------------------------
__global__ void __launch_bounds__(256) coef_kernel(const float* __restrict__ W,
                                                   const float* __restrict__ b) {
    const int oc = blockIdx.x;
    const int ic = threadIdx.x;

    float S[2][9];
    const int ER[3][2] = { {2,3}, {0,3}, {0,1} };
    #pragma unroll
    for (int w = 0; w < 2; w++) {
        float T = 0.0f;
        #pragma unroll
        for (int k = 0; k < BPC; k++) T += g_part[w][ic][k];
        float rs0 = g_row[w][ic][0], rs1 = g_row[w][ic][1],
              rs2 = g_row[w][ic][2], rs3 = g_row[w][ic][3];
        float cs0 = g_col[w][ic][0], cs1 = g_col[w][ic][1],
              cs2 = g_col[w][ic][2], cs3 = g_col[w][ic][3];
        float Rex[3] = { rs2+rs3, rs0+rs3, rs0+rs1 };
        float Cex[3] = { cs2+cs3, cs0+cs3, cs0+cs1 };
        #pragma unroll
        for (int kh = 0; kh < 3; kh++)
            #pragma unroll
            for (int kw = 0; kw < 3; kw++) {
                float cor = 0.0f;
                #pragma unroll
                for (int i = 0; i < 2; i++)
                    #pragma unroll
                    for (int j = 0; j < 2; j++)
                        cor += g_corn[w][ic][ER[kh][i]*4 + ER[kw][j]];
                S[w][kh*3 + kw] = T - Rex[kh] - Cex[kw] + cor;
            }
    }

    const float* wrow = W + (size_t)oc * CCH * 9 + ic * 9;
    float d1 = 0.0f, d2 = 0.0f;
    #pragma unroll
    for (int k = 0; k < 9; k++) {
        float w = wrow[k];
        d1 += w * S[0][k];
        d2 += w * S[1][k];
    }
    #pragma unroll
    for (int off = 16; off > 0; off >>= 1) {
        d1 += __shfl_down_sync(0xffffffffu, d1, off);
        d2 += __shfl_down_sync(0xffffffffu, d2, off);
    }
    __shared__ float s1[8], s2[8];
    int warp = ic >> 5, lane = ic & 31;
    if (lane == 0) { s1[warp] = d1; s2[warp] = d2; }
    __syncthreads();
    if (ic == 0) {
        float D1 = 0.0f, D2 = 0.0f;
        #pragma unroll
        for (int w = 0; w < 8; w++) { D1 += s1[w]; D2 += s2[w]; }
        float bb = b[oc];
        float m1 = bb + D1 * INVN;
        float m2 = bb + D2 * INVN;
        float m3 = bb + (D1 + D2) * INVN;
        float x1 = 1.0f / (1.0f + expf(-m1));
        float x2 = 1.0f / (1.0f + expf(-m2));
        float x3 = 1.0f / (1.0f + expf(-m3));
        bool c1 = (x1 >= x2);
        bool c2 = (x1 <= x2);
        float a1 = (c1 && (x1 >= x3)) ? 1.0f : 0.0f;
        float a2 = (c2 && (x2 >= x3)) ? 1.0f : 0.0f;
        float a3 = ((c1 && (x1 < x3)) || (c2 && (x2 < x3))) ? 1.0f : 0.0f;
        g_cf[0][oc] = a1 + a3;   // multiplies input1
        g_cf[1][oc] = a2 + a3;   // multiplies input2
    }
}

// ---------------------------------------------------------------------------
// Kernel 4: fixup, 4-quad wide (R15's proven shape). Presum already wrote
// out = in1+in2 (final for (1,1) channels). Single-input channels overwrite
// with a pure copy; (1,1) blocks exit after 2 scalar loads. Block-uniform,
// deterministic for fixed inputs -> graph-safe.
// ---------------------------------------------------------------------------
__global__ void __launch_bounds__(256) fixup_kernel(const float4* __restrict__ in1,
                                                    const float4* __restrict__ in2,
                                                    float4* __restrict__ out) {
    const int ch = blockIdx.x / BPC;
    const float k1 = g_cf[0][ch];
    const float k2 = g_cf[1][ch];
    if (k1 != 0.0f && k2 != 0.0f) return;        // (1,1): presum is final
    const float4* src = (k2 == 0.0f) ? in1 : in2;
    const size_t base = (size_t)blockIdx.x * QPB + threadIdx.x;
    float4 v0 = __ldcs(src + base);
    float4 v1 = __ldcs(src + base + 256);
    float4 v2 = __ldcs(src + base + 512);
    float4 v3 = __ldcs(src + base + 768);
    __stcs(out + base,       v0);
    __stcs(out + base + 256, v1);
    __stcs(out + base + 512, v2);
    __stcs(out + base + 768, v3);
}

extern "C" void kernel_launch(void* const* d_in, const int* in_sizes, int n_in,
                              void* d_out, int out_size) {
    const float* in1 = (const float*)d_in[0];
    const float* in2 = (const float*)d_in[1];
    const float* W   = (const float*)d_in[2];
    const float* b   = (const float*)d_in[3];
    float4* out = (float4*)d_out;

    border_kernel<<<dim3(CCH, 2), 128>>>(in1, in2);
    presum_kernel<<<CCH * BPC, 256>>>((const float4*)in1, (const float4*)in2, out);
    coef_kernel<<<CCH, 256>>>(W, b);
    fixup_kernel<<<CCH * BPC, 256>>>((const float4*)in1, (const float4*)in2, out);
}